// round 12
// baseline (speedup 1.0000x reference)
#include <cuda_runtime.h>
#include <cstddef>

// CAN: per-sample 2-layer MLP, B=16384, N=50, D=16, fp32.
// x = relu(x @ W0 + b0); x = relu(x @ W1 + b1)
//
// R11: occupancy build. Quad (rg, ch) -> lane owns 5 rows x 4 cols
// (40 lanes/sample), TPB=320, ~50 regs -> 4 blocks/SM = 40 warps (62.5%).
// cp.async staging; bias folded into d=0 FFMA; layer-0 in-place
// (quad-private, __syncwarp); layer-1 stores straight from accumulators.

#define CAN_D 16
#define CAN_N 50
#define SPB 8                 // samples per block
#define TPB 320               // 8 samples * 40 lanes
#define XBLK 84               // floats per 5-row block (80 data + 4 pad)
#define X_STRIDE 840          // 10 blocks * 84 floats per sample
#define W_FLOATS 544
#define W_STRIDE 560          // mod 32 banks = 16 -> straddle-conflict-free

__device__ __forceinline__ void cp_async16(unsigned dst, const void* src) {
    asm volatile("cp.async.cg.shared.global [%0], [%1], 16;"
                 :: "r"(dst), "l"(src));
}

// One layer for lane's 5 rows x 4 cols, scalar FFMA, bias folded into d=0.
// wl: float4 view of layer params (W row d quarter ch at idx 4d+ch, bias
// quarter at 64+ch). xrow: lane's 5 rows in smem, stride 16 floats.
__device__ __forceinline__ void can_core(const float4* __restrict__ wl,
                                         const float* __restrict__ xrow,
                                         int ch, float acc[5][4])
{
    // ---- chunk 0 (d = 0..3), d=0 uses bias as FFMA addend ----
    {
        const float4 bv = wl[64 + ch];
        float4 w0 = wl[0 * 4 + ch];
        float4 w1 = wl[1 * 4 + ch];
        float4 w2 = wl[2 * 4 + ch];
        float4 w3 = wl[3 * 4 + ch];
        #pragma unroll
        for (int r = 0; r < 5; ++r) {
            float4 xv = *reinterpret_cast<const float4*>(xrow + r * 16);
            acc[r][0] = fmaf(xv.x, w0.x, bv.x);
            acc[r][1] = fmaf(xv.x, w0.y, bv.y);
            acc[r][2] = fmaf(xv.x, w0.z, bv.z);
            acc[r][3] = fmaf(xv.x, w0.w, bv.w);
            acc[r][0] = fmaf(xv.y, w1.x, acc[r][0]);
            acc[r][1] = fmaf(xv.y, w1.y, acc[r][1]);
            acc[r][2] = fmaf(xv.y, w1.z, acc[r][2]);
            acc[r][3] = fmaf(xv.y, w1.w, acc[r][3]);
            acc[r][0] = fmaf(xv.z, w2.x, acc[r][0]);
            acc[r][1] = fmaf(xv.z, w2.y, acc[r][1]);
            acc[r][2] = fmaf(xv.z, w2.z, acc[r][2]);
            acc[r][3] = fmaf(xv.z, w2.w, acc[r][3]);
            acc[r][0] = fmaf(xv.w, w3.x, acc[r][0]);
            acc[r][1] = fmaf(xv.w, w3.y, acc[r][1]);
            acc[r][2] = fmaf(xv.w, w3.z, acc[r][2]);
            acc[r][3] = fmaf(xv.w, w3.w, acc[r][3]);
        }
    }
    // ---- chunks 1..3 (d = 4..15) ----
    #pragma unroll
    for (int dc = 1; dc < 4; ++dc) {
        float4 w0 = wl[(4 * dc + 0) * 4 + ch];
        float4 w1 = wl[(4 * dc + 1) * 4 + ch];
        float4 w2 = wl[(4 * dc + 2) * 4 + ch];
        float4 w3 = wl[(4 * dc + 3) * 4 + ch];
        #pragma unroll
        for (int r = 0; r < 5; ++r) {
            float4 xv = *reinterpret_cast<const float4*>(xrow + r * 16 + 4 * dc);
            acc[r][0] = fmaf(xv.x, w0.x, acc[r][0]);
            acc[r][1] = fmaf(xv.x, w0.y, acc[r][1]);
            acc[r][2] = fmaf(xv.x, w0.z, acc[r][2]);
            acc[r][3] = fmaf(xv.x, w0.w, acc[r][3]);
            acc[r][0] = fmaf(xv.y, w1.x, acc[r][0]);
            acc[r][1] = fmaf(xv.y, w1.y, acc[r][1]);
            acc[r][2] = fmaf(xv.y, w1.z, acc[r][2]);
            acc[r][3] = fmaf(xv.y, w1.w, acc[r][3]);
            acc[r][0] = fmaf(xv.z, w2.x, acc[r][0]);
            acc[r][1] = fmaf(xv.z, w2.y, acc[r][1]);
            acc[r][2] = fmaf(xv.z, w2.z, acc[r][2]);
            acc[r][3] = fmaf(xv.z, w2.w, acc[r][3]);
            acc[r][0] = fmaf(xv.w, w3.x, acc[r][0]);
            acc[r][1] = fmaf(xv.w, w3.y, acc[r][1]);
            acc[r][2] = fmaf(xv.w, w3.z, acc[r][2]);
            acc[r][3] = fmaf(xv.w, w3.w, acc[r][3]);
        }
    }
}

__global__ __launch_bounds__(TPB, 4)
void can_kernel(const float* __restrict__ user,
                const float* __restrict__ item,
                float* __restrict__ out,
                int B)
{
    __shared__ __align__(16) float xs[SPB * X_STRIDE];   // 26.9 KB
    __shared__ __align__(16) float ws[SPB * W_STRIDE];   // 17.9 KB

    const int tid   = threadIdx.x;
    const int sbase = blockIdx.x * SPB;
    const int nsamp = min(SPB, B - sbase);
    const int nf4   = nsamp * 200;                        // <= 1600
    const int nw4   = nsamp * 136;                        // <= 1088

    // ---- stage x and W via cp.async (no register round-trip) ----
    {
        const float4* __restrict__ gx =
            reinterpret_cast<const float4*>(user + (size_t)sbase * (CAN_N * CAN_D));
        #pragma unroll
        for (int k = 0; k < 5; ++k) {
            int i = tid + k * TPB;
            if (i < nf4) {
                int s = i / 200, f = i - s * 200;
                int row = f >> 2, q = f & 3;
                int rb = row / 5, rr = row - rb * 5;
                unsigned dst = (unsigned)__cvta_generic_to_shared(
                    xs + s * X_STRIDE + rb * XBLK + rr * 16 + q * 4);
                cp_async16(dst, gx + i);
            }
        }
        const float4* __restrict__ gw =
            reinterpret_cast<const float4*>(item + (size_t)sbase * W_FLOATS);
        #pragma unroll
        for (int k = 0; k < 4; ++k) {
            int i = tid + k * TPB;
            if (i < nw4) {
                int s = i / 136, f = i - s * 136;
                unsigned dst = (unsigned)__cvta_generic_to_shared(
                    ws + s * W_STRIDE + f * 4);
                cp_async16(dst, gw + i);
            }
        }
        asm volatile("cp.async.commit_group;" ::: "memory");
        asm volatile("cp.async.wait_group 0;"  ::: "memory");
    }
    __syncthreads();

    const int sl = tid / 40;        // local sample
    const int ls = tid - sl * 40;
    const int rg = ls >> 2;         // row group: rows rg*5 .. rg*5+4
    const int ch = ls & 3;          // column quarter: cols ch*4 .. ch*4+3

    if (sl < nsamp) {
        const float4* __restrict__ wl =
            reinterpret_cast<const float4*>(ws + sl * W_STRIDE);
        float* __restrict__ xrow = xs + sl * X_STRIDE + rg * XBLK;
        float acc[5][4];

        // ---- layer 0: accumulate, relu, write own quarter back in place ----
        can_core(wl, xrow, ch, acc);
        __syncwarp();               // quad finishes reading before overwrite
        #pragma unroll
        for (int r = 0; r < 5; ++r) {
            *reinterpret_cast<float4*>(xrow + r * 16 + ch * 4) =
                make_float4(fmaxf(acc[r][0], 0.f), fmaxf(acc[r][1], 0.f),
                            fmaxf(acc[r][2], 0.f), fmaxf(acc[r][3], 0.f));
        }
        __syncwarp();               // quad writes visible before layer-1 reads

        // ---- layer 1: accumulate, relu, store straight to global ----
        can_core(wl + 68, xrow, ch, acc);   // layer-1 params at +272 floats
        float* __restrict__ gout = out + (size_t)(sbase + sl) * (CAN_N * CAN_D)
                                 + (rg * 5) * CAN_D + ch * 4;
        #pragma unroll
        for (int r = 0; r < 5; ++r) {
            *reinterpret_cast<float4*>(gout + r * CAN_D) =
                make_float4(fmaxf(acc[r][0], 0.f), fmaxf(acc[r][1], 0.f),
                            fmaxf(acc[r][2], 0.f), fmaxf(acc[r][3], 0.f));
        }
    }
}

extern "C" void kernel_launch(void* const* d_in, const int* in_sizes, int n_in,
                              void* d_out, int out_size)
{
    const float* user = (const float*)d_in[0];
    const float* item = (const float*)d_in[1];
    float* out = (float*)d_out;

    const int B = in_sizes[0] / (CAN_N * CAN_D);   // 16384
    const int grid = (B + SPB - 1) / SPB;

    can_kernel<<<grid, TPB>>>(user, item, out, B);
}

// round 13
// speedup vs baseline: 1.3628x; 1.3628x over previous
#include <cuda_runtime.h>
#include <cstddef>

// CAN: per-sample 2-layer MLP, B=16384, N=50, D=16, fp32.
// x = relu(x @ W0 + b0); x = relu(x @ W1 + b1)
//
// R12: R10 core (quad lane owns 10 rows x 4 cols, cp.async staging, bias
// folded into d=0 FFMA, in-place layer-0, direct STG layer-1) + software
// pipelining: W chunk dc+1 prefetched during chunk dc's FMA burst, x row
// r+1 prefetched during row r's FMAs.

#define CAN_D 16
#define CAN_N 50
#define SPB 8                 // samples per block
#define TPB 160               // 8 samples * 20 lanes
#define XBLK 164              // floats per 10-row block (160 data + 4 pad)
#define X_STRIDE 820          // 5 blocks * 164 floats per sample
#define W_FLOATS 544
#define W_STRIDE 560          // mod 32 banks = 16 -> straddle-conflict-free

__device__ __forceinline__ void cp_async16(unsigned dst, const void* src) {
    asm volatile("cp.async.cg.shared.global [%0], [%1], 16;"
                 :: "r"(dst), "l"(src));
}

// FMA a row's 4-d slice (xv) against W window (w0..w3) into acc[4].
__device__ __forceinline__ void row_fma(const float4& xv,
                                        const float4& w0, const float4& w1,
                                        const float4& w2, const float4& w3,
                                        float acc[4])
{
    acc[0] = fmaf(xv.x, w0.x, acc[0]);
    acc[1] = fmaf(xv.x, w0.y, acc[1]);
    acc[2] = fmaf(xv.x, w0.z, acc[2]);
    acc[3] = fmaf(xv.x, w0.w, acc[3]);
    acc[0] = fmaf(xv.y, w1.x, acc[0]);
    acc[1] = fmaf(xv.y, w1.y, acc[1]);
    acc[2] = fmaf(xv.y, w1.z, acc[2]);
    acc[3] = fmaf(xv.y, w1.w, acc[3]);
    acc[0] = fmaf(xv.z, w2.x, acc[0]);
    acc[1] = fmaf(xv.z, w2.y, acc[1]);
    acc[2] = fmaf(xv.z, w2.z, acc[2]);
    acc[3] = fmaf(xv.z, w2.w, acc[3]);
    acc[0] = fmaf(xv.w, w3.x, acc[0]);
    acc[1] = fmaf(xv.w, w3.y, acc[1]);
    acc[2] = fmaf(xv.w, w3.z, acc[2]);
    acc[3] = fmaf(xv.w, w3.w, acc[3]);
}

// One layer for lane's 10 rows x 4 cols, scalar FFMA, W-chunk + x-row
// software pipelining. Bias folded in via acc init (4 movs, simpler reg
// allocation than FFMA-addend under prefetch pressure).
__device__ __forceinline__ void can_core(const float4* __restrict__ wl,
                                         const float* __restrict__ xrow,
                                         int ch, float acc[10][4])
{
    const float4 bv = wl[64 + ch];
    #pragma unroll
    for (int r = 0; r < 10; ++r) {
        acc[r][0] = bv.x; acc[r][1] = bv.y; acc[r][2] = bv.z; acc[r][3] = bv.w;
    }

    // prologue: W chunk 0
    float4 w0 = wl[0 * 4 + ch];
    float4 w1 = wl[1 * 4 + ch];
    float4 w2 = wl[2 * 4 + ch];
    float4 w3 = wl[3 * 4 + ch];

    #pragma unroll
    for (int dc = 0; dc < 4; ++dc) {
        // prefetch next W chunk before this chunk's FMA burst
        float4 n0, n1, n2, n3;
        if (dc < 3) {
            n0 = wl[(4 * dc + 4) * 4 + ch];
            n1 = wl[(4 * dc + 5) * 4 + ch];
            n2 = wl[(4 * dc + 6) * 4 + ch];
            n3 = wl[(4 * dc + 7) * 4 + ch];
        }
        // x pipelined by one row
        float4 xv = *reinterpret_cast<const float4*>(xrow + 0 * 16 + 4 * dc);
        #pragma unroll
        for (int r = 0; r < 10; ++r) {
            float4 xn;
            if (r < 9)
                xn = *reinterpret_cast<const float4*>(xrow + (r + 1) * 16 + 4 * dc);
            row_fma(xv, w0, w1, w2, w3, acc[r]);
            xv = xn;
        }
        if (dc < 3) { w0 = n0; w1 = n1; w2 = n2; w3 = n3; }
    }
}

__global__ __launch_bounds__(TPB, 5)
void can_kernel(const float* __restrict__ user,
                const float* __restrict__ item,
                float* __restrict__ out,
                int B)
{
    __shared__ __align__(16) float xs[SPB * X_STRIDE];   // 26.2 KB
    __shared__ __align__(16) float ws[SPB * W_STRIDE];   // 17.9 KB

    const int tid   = threadIdx.x;
    const int sbase = blockIdx.x * SPB;
    const int nsamp = min(SPB, B - sbase);
    const int nf4   = nsamp * 200;                        // <= 1600
    const int nw4   = nsamp * 136;                        // <= 1088

    // ---- stage x and W via cp.async ----
    {
        const float4* __restrict__ gx =
            reinterpret_cast<const float4*>(user + (size_t)sbase * (CAN_N * CAN_D));
        #pragma unroll
        for (int k = 0; k < 10; ++k) {
            int i = tid + k * TPB;
            if (i < nf4) {
                int s = i / 200, f = i - s * 200;
                int row = f >> 2, q = f & 3;
                int rb = row / 10, rr = row - rb * 10;
                unsigned dst = (unsigned)__cvta_generic_to_shared(
                    xs + s * X_STRIDE + rb * XBLK + rr * 16 + q * 4);
                cp_async16(dst, gx + i);
            }
        }
        const float4* __restrict__ gw =
            reinterpret_cast<const float4*>(item + (size_t)sbase * W_FLOATS);
        #pragma unroll
        for (int k = 0; k < 7; ++k) {
            int i = tid + k * TPB;
            if (i < nw4) {
                int s = i / 136, f = i - s * 136;
                unsigned dst = (unsigned)__cvta_generic_to_shared(
                    ws + s * W_STRIDE + f * 4);
                cp_async16(dst, gw + i);
            }
        }
        asm volatile("cp.async.commit_group;" ::: "memory");
        asm volatile("cp.async.wait_group 0;"  ::: "memory");
    }
    __syncthreads();

    const int sl = tid / 20;        // local sample
    const int ls = tid - sl * 20;
    const int rg = ls >> 2;         // row group: rows rg*10 .. rg*10+9
    const int ch = ls & 3;          // column quarter: cols ch*4 .. ch*4+3

    if (sl < nsamp) {
        const float4* __restrict__ wl =
            reinterpret_cast<const float4*>(ws + sl * W_STRIDE);
        float* __restrict__ xrow = xs + sl * X_STRIDE + rg * XBLK;
        float acc[10][4];

        // ---- layer 0: accumulate, relu, write own quarter back in place ----
        can_core(wl, xrow, ch, acc);
        __syncwarp();               // quad finishes reading before overwrite
        #pragma unroll
        for (int r = 0; r < 10; ++r) {
            *reinterpret_cast<float4*>(xrow + r * 16 + ch * 4) =
                make_float4(fmaxf(acc[r][0], 0.f), fmaxf(acc[r][1], 0.f),
                            fmaxf(acc[r][2], 0.f), fmaxf(acc[r][3], 0.f));
        }
        __syncwarp();               // quad writes visible before layer-1 reads

        // ---- layer 1: accumulate, relu, store straight to global ----
        can_core(wl + 68, xrow, ch, acc);   // layer-1 params at +272 floats
        float* __restrict__ gout = out + (size_t)(sbase + sl) * (CAN_N * CAN_D)
                                 + (rg * 10) * CAN_D + ch * 4;
        #pragma unroll
        for (int r = 0; r < 10; ++r) {
            *reinterpret_cast<float4*>(gout + r * CAN_D) =
                make_float4(fmaxf(acc[r][0], 0.f), fmaxf(acc[r][1], 0.f),
                            fmaxf(acc[r][2], 0.f), fmaxf(acc[r][3], 0.f));
        }
    }
}

extern "C" void kernel_launch(void* const* d_in, const int* in_sizes, int n_in,
                              void* d_out, int out_size)
{
    const float* user = (const float*)d_in[0];
    const float* item = (const float*)d_in[1];
    float* out = (float*)d_out;

    const int B = in_sizes[0] / (CAN_N * CAN_D);   // 16384
    const int grid = (B + SPB - 1) / SPB;

    can_kernel<<<grid, TPB>>>(user, item, out, B);
}